// round 1
// baseline (speedup 1.0000x reference)
#include <cuda_runtime.h>
#include <math.h>

#define NN 30000
#define EE 480000
#define HID 256
#define HEADS 8
#define OUTC 32
#define LAYERS 6
#define BN_EPS 1e-5f

// ---------------- scratch (static device globals; no allocs allowed) ----------------
__device__ float g_h[NN * HID];
__device__ float g_xl[NN * HID];
__device__ float g_xr[NN * HID];
__device__ float g_agg[NN * HID];
__device__ float g_t1[NN * 128];
__device__ float g_ea0[EE * HID];
__device__ float g_ea1[EE * HID];
__device__ float g_ep[EE * HID];
__device__ float g_logits[EE * HEADS];
__device__ float g_exv[EE * HEADS];
__device__ int   g_mx[NN * HEADS];
__device__ float g_den[NN * HEADS];

// ---------------- SGEMM: C[M,N] = A[M,K] @ B[K,N] (+bias) with optional leaky ----------------
// 128x128 tile, BK=8, 256 threads, 8x8 microtile.
__global__ __launch_bounds__(256) void sgemm(
    const float* __restrict__ A, const float* __restrict__ B,
    const float* __restrict__ bias, float* __restrict__ C,
    int M, int N, int K, float slope)
{
    const int BM = 128, BNt = 128, BK = 8;
    __shared__ float As[BK][BM];
    __shared__ float Bs[BK][BNt];

    int tid = threadIdx.x;
    int tx = tid & 15;     // 16 col-groups
    int ty = tid >> 4;     // 16 row-groups
    int rowBase = blockIdx.y * BM;
    int colBase = blockIdx.x * BNt;

    float acc[8][8];
#pragma unroll
    for (int i = 0; i < 8; i++)
#pragma unroll
        for (int j = 0; j < 8; j++) acc[i][j] = 0.f;

    for (int k0 = 0; k0 < K; k0 += BK) {
        // load A tile: 128x8
#pragma unroll
        for (int it = 0; it < 4; it++) {
            int idx = tid + it * 256;          // 0..1023
            int m = idx >> 3, kk = idx & 7;
            int gr = rowBase + m, gc = k0 + kk;
            As[kk][m] = (gr < M && gc < K) ? A[(size_t)gr * K + gc] : 0.f;
        }
        // load B tile: 8x128 (coalesced along N)
#pragma unroll
        for (int it = 0; it < 4; it++) {
            int idx = tid + it * 256;
            int kk = idx >> 7, n = idx & 127;
            int gr = k0 + kk, gc = colBase + n;
            Bs[kk][n] = (gr < K && gc < N) ? B[(size_t)gr * N + gc] : 0.f;
        }
        __syncthreads();
#pragma unroll
        for (int kk = 0; kk < BK; kk++) {
            float a[8], b[8];
#pragma unroll
            for (int i = 0; i < 8; i++) a[i] = As[kk][ty * 8 + i];
#pragma unroll
            for (int j = 0; j < 8; j++) b[j] = Bs[kk][tx * 8 + j];
#pragma unroll
            for (int i = 0; i < 8; i++)
#pragma unroll
                for (int j = 0; j < 8; j++) acc[i][j] += a[i] * b[j];
        }
        __syncthreads();
    }

#pragma unroll
    for (int i = 0; i < 8; i++) {
        int gr = rowBase + ty * 8 + i;
        if (gr >= M) continue;
#pragma unroll
        for (int j = 0; j < 8; j++) {
            int gc = colBase + tx * 8 + j;
            if (gc >= N) continue;
            float v = acc[i][j];
            if (bias) v += bias[gc];
            v = (v >= 0.f) ? v : slope * v;   // slope==1.f -> identity
            C[(size_t)gr * N + gc] = v;
        }
    }
}

// ---------------- per-(node,head) softmax state init ----------------
__global__ void init_softmax(int* __restrict__ mx, float* __restrict__ den, int n)
{
    int i = blockIdx.x * blockDim.x + threadIdx.x;
    if (i < n) { mx[i] = (int)0xFF800000u; den[i] = 0.f; }  // -inf bits
}

// order-preserving float atomic max on int-encoded storage
__device__ __forceinline__ void atomicMaxFloatBits(int* addr, float val)
{
    if (val >= 0.f) atomicMax(addr, __float_as_int(val));
    else            atomicMin((unsigned int*)addr, __float_as_uint(val));
}

// ---------------- pass A: logits + segment max ----------------
// one block per edge, 256 threads; warp h handles head h (lanes = channels)
__global__ __launch_bounds__(256) void edge_logits_kernel(
    const float* __restrict__ xl, const float* __restrict__ xr,
    const float* __restrict__ ep, const int* __restrict__ src,
    const int* __restrict__ dst, const float* __restrict__ att,
    float* __restrict__ logits, int* __restrict__ mx)
{
    int e = blockIdx.x;
    int t = threadIdx.x;
    int s = src[e], d = dst[e];
    float m = xl[(size_t)s * HID + t] + xr[(size_t)d * HID + t] + ep[(size_t)e * HID + t];
    m = (m >= 0.f) ? m : 0.2f * m;
    float v = m * att[t];
#pragma unroll
    for (int off = 16; off; off >>= 1) v += __shfl_xor_sync(0xffffffffu, v, off);
    if ((t & 31) == 0) {
        int h = t >> 5;
        logits[(size_t)e * HEADS + h] = v;
        atomicMaxFloatBits(&mx[d * HEADS + h], v);
    }
}

// ---------------- pass B: exp + segment sum ----------------
__global__ void edge_exp_kernel(
    const float* __restrict__ logits, const int* __restrict__ dst,
    const int* __restrict__ mx, float* __restrict__ exv, float* __restrict__ den)
{
    int i = blockIdx.x * blockDim.x + threadIdx.x;
    if (i >= EE * HEADS) return;
    int e = i >> 3, h = i & 7;
    int d = dst[e];
    float v = expf(logits[i] - __int_as_float(mx[d * HEADS + h]));
    exv[i] = v;
    atomicAdd(&den[d * HEADS + h], v);
}

// ---------------- pass C: weighted aggregation ----------------
__global__ __launch_bounds__(256) void edge_agg_kernel(
    const float* __restrict__ xl, const float* __restrict__ exv,
    const float* __restrict__ den, const int* __restrict__ src,
    const int* __restrict__ dst, float* __restrict__ agg)
{
    int e = blockIdx.x;
    int t = threadIdx.x;
    int s = src[e], d = dst[e];
    int h = t >> 5;
    float alpha = exv[(size_t)e * HEADS + h] / (den[d * HEADS + h] + 1e-16f);
    atomicAdd(&agg[(size_t)d * HID + t], xl[(size_t)s * HID + t] * alpha);
}

// ---------------- node update: conv bias, BN(eval), leaky, residual ----------------
__global__ void node_update_kernel(
    const float* __restrict__ agg, const float* __restrict__ conv_b,
    const float* __restrict__ bn_g, const float* __restrict__ bn_b,
    const float* __restrict__ bn_rm, const float* __restrict__ bn_rv,
    float* __restrict__ h, int layer)
{
    int i = blockIdx.x * blockDim.x + threadIdx.x;
    if (i >= NN * HID) return;
    int c = i & (HID - 1);
    float v = agg[i] + conv_b[c];
    v = (v - bn_rm[c]) * rsqrtf(bn_rv[c] + BN_EPS) * bn_g[c] + bn_b[c];
    v = (v >= 0.f) ? v : 0.01f * v;
    if (layer >= 1) v += h[i];
    h[i] = v;
}

// ---------------- final projection: out = t1 @ W2 + b2, warp per row ----------------
__global__ void final_out_kernel(
    const float* __restrict__ t1, const float* __restrict__ W2,
    const float* __restrict__ b2, float* __restrict__ out)
{
    int gw = (blockIdx.x * blockDim.x + threadIdx.x) >> 5;
    int lane = threadIdx.x & 31;
    if (gw >= NN) return;
    const float* row = t1 + (size_t)gw * 128;
    float acc = 0.f;
#pragma unroll
    for (int k = lane; k < 128; k += 32) acc += row[k] * W2[k];
#pragma unroll
    for (int off = 16; off; off >>= 1) acc += __shfl_xor_sync(0xffffffffu, acc, off);
    if (lane == 0) out[gw] = acc + b2[0];
}

// ---------------- launch ----------------
extern "C" void kernel_launch(void* const* d_in, const int* in_sizes, int n_in,
                              void* d_out, int out_size)
{
    const float* x         = (const float*)d_in[0];
    const int*   ei        = (const int*)  d_in[1];
    const float* edge_attr = (const float*)d_in[2];
    const float* node_W    = (const float*)d_in[3];
    const float* node_b    = (const float*)d_in[4];
    const float* edge_W    = (const float*)d_in[5];
    const float* edge_b    = (const float*)d_in[6];
    const float* Wl        = (const float*)d_in[7];
    const float* bl        = (const float*)d_in[8];
    const float* Wr        = (const float*)d_in[9];
    const float* br        = (const float*)d_in[10];
    const float* We        = (const float*)d_in[11];
    const float* att       = (const float*)d_in[12];
    const float* conv_b    = (const float*)d_in[13];
    const float* Weu       = (const float*)d_in[14];
    const float* beu       = (const float*)d_in[15];
    const float* bn_g      = (const float*)d_in[16];
    const float* bn_b      = (const float*)d_in[17];
    const float* bn_rm     = (const float*)d_in[18];
    const float* bn_rv     = (const float*)d_in[19];
    const float* out_W1    = (const float*)d_in[20];
    const float* out_b1    = (const float*)d_in[21];
    const float* out_W2    = (const float*)d_in[22];
    const float* out_b2    = (const float*)d_in[23];

    const int* src = ei;         // edge_index[0]
    const int* dst = ei + EE;    // edge_index[1]

    float *h, *xl, *xr, *agg, *t1, *ea0, *ea1, *ep, *logits, *exv, *den;
    int *mx;
    cudaGetSymbolAddress((void**)&h,      g_h);
    cudaGetSymbolAddress((void**)&xl,     g_xl);
    cudaGetSymbolAddress((void**)&xr,     g_xr);
    cudaGetSymbolAddress((void**)&agg,    g_agg);
    cudaGetSymbolAddress((void**)&t1,     g_t1);
    cudaGetSymbolAddress((void**)&ea0,    g_ea0);
    cudaGetSymbolAddress((void**)&ea1,    g_ea1);
    cudaGetSymbolAddress((void**)&ep,     g_ep);
    cudaGetSymbolAddress((void**)&logits, g_logits);
    cudaGetSymbolAddress((void**)&exv,    g_exv);
    cudaGetSymbolAddress((void**)&mx,     g_mx);
    cudaGetSymbolAddress((void**)&den,    g_den);

    dim3 blk(256);
    dim3 gN((HID + 127) / 128, (NN + 127) / 128);
    dim3 gE((HID + 127) / 128, (EE + 127) / 128);
    dim3 gO((128 + 127) / 128, (NN + 127) / 128);

    // input encoders
    sgemm<<<gN, blk>>>(x,         node_W, node_b, h,   NN, HID, 13, 1.f);
    sgemm<<<gE, blk>>>(edge_attr, edge_W, edge_b, ea0, EE, HID, 10, 1.f);

    float* ea_cur = ea0;
    float* ea_nxt = ea1;

    for (int i = 0; i < LAYERS; i++) {
        const float* Wli  = Wl  + (size_t)i * HID * HID;
        const float* Wri  = Wr  + (size_t)i * HID * HID;
        const float* Wei  = We  + (size_t)i * HID * HID;
        const float* Weui = Weu + (size_t)i * HID * HID;

        sgemm<<<gN, blk>>>(h,      Wli, bl + i * HID, xl, NN, HID, HID, 1.f);
        sgemm<<<gN, blk>>>(h,      Wri, br + i * HID, xr, NN, HID, HID, 1.f);
        sgemm<<<gE, blk>>>(ea_cur, Wei, nullptr,      ep, EE, HID, HID, 1.f);

        init_softmax<<<(NN * HEADS + 255) / 256, 256>>>(mx, den, NN * HEADS);
        cudaMemsetAsync(agg, 0, (size_t)NN * HID * sizeof(float), 0);

        edge_logits_kernel<<<EE, 256>>>(xl, xr, ep, src, dst,
                                        att + (size_t)i * HEADS * OUTC, logits, mx);
        edge_exp_kernel<<<(EE * HEADS + 255) / 256, 256>>>(logits, dst, mx, exv, den);
        edge_agg_kernel<<<EE, 256>>>(xl, exv, den, src, dst, agg);

        node_update_kernel<<<(NN * HID + 255) / 256, 256>>>(
            agg, conv_b + i * HID, bn_g + i * HID, bn_b + i * HID,
            bn_rm + i * HID, bn_rv + i * HID, h, i);

        if (i < LAYERS - 1) {  // ea after last layer is dead — skip 62.9 GF
            sgemm<<<gE, blk>>>(ea_cur, Weui, beu + i * HID, ea_nxt, EE, HID, HID, 1.f);
            float* tmp = ea_cur; ea_cur = ea_nxt; ea_nxt = tmp;
        }
    }

    sgemm<<<gO, blk>>>(h, out_W1, out_b1, t1, NN, 128, HID, 0.01f);
    final_out_kernel<<<(NN * 32 + 255) / 256, 256>>>(t1, out_W2, out_b2, (float*)d_out);
}

// round 2
// speedup vs baseline: 7.0335x; 7.0335x over previous
#include <cuda_runtime.h>
#include <math.h>

#define NN 30000
#define EE 480000
#define HID 256
#define HEADS 8
#define LAYERS 6
#define BN_EPS 1e-5f

// ---------------- scratch (static device globals; no allocs allowed) ----------------
__device__ float g_h[NN * HID];
__device__ float g_xl[NN * HID];
__device__ float g_xr[NN * HID];
__device__ float g_agg[NN * HID];
__device__ float g_t1[NN * 128];
__device__ float g_logits[EE * HEADS];
__device__ float g_exv[EE * HEADS];
__device__ int   g_mx[NN * HEADS];
__device__ float g_den[NN * HEADS];
// edge-chain precompute: ep_i = edge_attr @ R_i + r_i
__device__ float g_R[LAYERS * 10 * HID];
__device__ float g_r[LAYERS * HID];
__device__ float g_A0[10 * HID];
__device__ float g_A1[10 * HID];
__device__ float g_b0[HID];
__device__ float g_b1[HID];

// ---------------- SGEMM: C[M,N] = A[M,K] @ B[K,N] (+bias) with optional leaky ----------------
__global__ __launch_bounds__(256) void sgemm(
    const float* __restrict__ A, const float* __restrict__ B,
    const float* __restrict__ bias, float* __restrict__ C,
    int M, int N, int K, float slope)
{
    const int BM = 128, BNt = 128, BK = 8;
    __shared__ float As[BK][BM];
    __shared__ float Bs[BK][BNt];

    int tid = threadIdx.x;
    int tx = tid & 15;
    int ty = tid >> 4;
    int rowBase = blockIdx.y * BM;
    int colBase = blockIdx.x * BNt;

    float acc[8][8];
#pragma unroll
    for (int i = 0; i < 8; i++)
#pragma unroll
        for (int j = 0; j < 8; j++) acc[i][j] = 0.f;

    for (int k0 = 0; k0 < K; k0 += BK) {
#pragma unroll
        for (int it = 0; it < 4; it++) {
            int idx = tid + it * 256;
            int m = idx >> 3, kk = idx & 7;
            int gr = rowBase + m, gc = k0 + kk;
            As[kk][m] = (gr < M && gc < K) ? A[(size_t)gr * K + gc] : 0.f;
        }
#pragma unroll
        for (int it = 0; it < 4; it++) {
            int idx = tid + it * 256;
            int kk = idx >> 7, n = idx & 127;
            int gr = k0 + kk, gc = colBase + n;
            Bs[kk][n] = (gr < K && gc < N) ? B[(size_t)gr * N + gc] : 0.f;
        }
        __syncthreads();
#pragma unroll
        for (int kk = 0; kk < BK; kk++) {
            float a[8], b[8];
#pragma unroll
            for (int i = 0; i < 8; i++) a[i] = As[kk][ty * 8 + i];
#pragma unroll
            for (int j = 0; j < 8; j++) b[j] = Bs[kk][tx * 8 + j];
#pragma unroll
            for (int i = 0; i < 8; i++)
#pragma unroll
                for (int j = 0; j < 8; j++) acc[i][j] += a[i] * b[j];
        }
        __syncthreads();
    }

#pragma unroll
    for (int i = 0; i < 8; i++) {
        int gr = rowBase + ty * 8 + i;
        if (gr >= M) continue;
#pragma unroll
        for (int j = 0; j < 8; j++) {
            int gc = colBase + tx * 8 + j;
            if (gc >= N) continue;
            float v = acc[i][j];
            if (bias) v += bias[gc];
            v = (v >= 0.f) ? v : slope * v;
            C[(size_t)gr * N + gc] = v;
        }
    }
}

// ---------------- tiny precompute GEMM: C[10,256] = A[10,256] @ W[256,256] ----------------
// one block per output row; threads = columns
__global__ __launch_bounds__(256) void gemm10(
    const float* __restrict__ A, const float* __restrict__ W, float* __restrict__ C)
{
    int r = blockIdx.x;        // 0..9
    int c = threadIdx.x;       // 0..255
    float acc = 0.f;
    const float* Ar = A + r * HID;
    for (int k = 0; k < HID; k++) acc += Ar[k] * W[(size_t)k * HID + c];
    C[r * HID + c] = acc;
}

// ---------------- vec-mat: out[c] = sum_k v[k]*W[k][c] (+ add[c]) ----------------
__global__ __launch_bounds__(256) void vecmat(
    const float* __restrict__ v, const float* __restrict__ W,
    const float* __restrict__ add, float* __restrict__ out)
{
    int c = threadIdx.x;
    float acc = add ? add[c] : 0.f;
    for (int k = 0; k < HID; k++) acc += v[k] * W[(size_t)k * HID + c];
    out[c] = acc;
}

// ---------------- softmax state init ----------------
__global__ void init_softmax(int* __restrict__ mx, float* __restrict__ den, int n)
{
    int i = blockIdx.x * blockDim.x + threadIdx.x;
    if (i < n) { mx[i] = (int)0xFF800000u; den[i] = 0.f; }
}

__device__ __forceinline__ void atomicMaxFloatBits(int* addr, float val)
{
    if (val >= 0.f) atomicMax(addr, __float_as_int(val));
    else            atomicMin((unsigned int*)addr, __float_as_uint(val));
}

__device__ __forceinline__ float leaky02(float v) { return v >= 0.f ? v : 0.2f * v; }

// ---------------- pass A: fused ep + logits + segment max ----------------
// block = (64, 4): 4 edges/block, 64 threads/edge, float4 channels
__global__ __launch_bounds__(256) void edge_logits_fused(
    const float4* __restrict__ xl4, const float4* __restrict__ xr4,
    const float* __restrict__ eattr, const float4* __restrict__ R4,
    const float4* __restrict__ rv4, const int* __restrict__ src,
    const int* __restrict__ dst, const float4* __restrict__ att4,
    float* __restrict__ logits, int* __restrict__ mx)
{
    int e = blockIdx.x * 4 + threadIdx.y;
    int t = threadIdx.x;                       // 0..63, channels 4t..4t+3
    int s = src[e], d = dst[e];

    // ep = edge_attr[e] (10) @ R + r
    float4 acc = rv4[t];
    const float* ea = eattr + (size_t)e * 10;
#pragma unroll
    for (int k = 0; k < 10; k++) {
        float a = ea[k];
        float4 rr = R4[k * 64 + t];
        acc.x += a * rr.x; acc.y += a * rr.y; acc.z += a * rr.z; acc.w += a * rr.w;
    }
    float4 l = xl4[(size_t)s * 64 + t];
    float4 rr = xr4[(size_t)d * 64 + t];
    float4 m;
    m.x = leaky02(l.x + rr.x + acc.x);
    m.y = leaky02(l.y + rr.y + acc.y);
    m.z = leaky02(l.z + rr.z + acc.z);
    m.w = leaky02(l.w + rr.w + acc.w);
    float4 at = att4[t];
    float p = m.x * at.x + m.y * at.y + m.z * at.z + m.w * at.w;
#pragma unroll
    for (int off = 4; off; off >>= 1) p += __shfl_xor_sync(0xffffffffu, p, off);
    if ((t & 7) == 0) {
        int h = t >> 3;
        logits[(size_t)e * HEADS + h] = p;
        atomicMaxFloatBits(&mx[d * HEADS + h], p);
    }
}

// ---------------- pass B: exp + segment sum ----------------
__global__ void edge_exp_kernel(
    const float* __restrict__ logits, const int* __restrict__ dst,
    const int* __restrict__ mx, float* __restrict__ exv, float* __restrict__ den)
{
    int i = blockIdx.x * blockDim.x + threadIdx.x;
    if (i >= EE * HEADS) return;
    int e = i >> 3, h = i & 7;
    int d = dst[e];
    float v = expf(logits[i] - __int_as_float(mx[d * HEADS + h]));
    exv[i] = v;
    atomicAdd(&den[d * HEADS + h], v);
}

// ---------------- pass C: weighted aggregation with vector atomics ----------------
__global__ __launch_bounds__(256) void edge_agg_kernel(
    const float4* __restrict__ xl4, const float* __restrict__ exv,
    const float* __restrict__ den, const int* __restrict__ src,
    const int* __restrict__ dst, float4* __restrict__ agg4)
{
    int e = blockIdx.x * 4 + threadIdx.y;
    int t = threadIdx.x;
    int s = src[e], d = dst[e];
    int h = t >> 3;
    float alpha = exv[(size_t)e * HEADS + h] / (den[d * HEADS + h] + 1e-16f);
    float4 v = xl4[(size_t)s * 64 + t];
    v.x *= alpha; v.y *= alpha; v.z *= alpha; v.w *= alpha;
    float4* addr = agg4 + (size_t)d * 64 + t;
    asm volatile("red.global.add.v4.f32 [%0], {%1, %2, %3, %4};"
                 :: "l"(addr), "f"(v.x), "f"(v.y), "f"(v.z), "f"(v.w) : "memory");
}

// ---------------- node update ----------------
__global__ void node_update_kernel(
    const float* __restrict__ agg, const float* __restrict__ conv_b,
    const float* __restrict__ bn_g, const float* __restrict__ bn_b,
    const float* __restrict__ bn_rm, const float* __restrict__ bn_rv,
    float* __restrict__ h, int layer)
{
    int i = blockIdx.x * blockDim.x + threadIdx.x;
    if (i >= NN * HID) return;
    int c = i & (HID - 1);
    float v = agg[i] + conv_b[c];
    v = (v - bn_rm[c]) * rsqrtf(bn_rv[c] + BN_EPS) * bn_g[c] + bn_b[c];
    v = (v >= 0.f) ? v : 0.01f * v;
    if (layer >= 1) v += h[i];
    h[i] = v;
}

// ---------------- final projection ----------------
__global__ void final_out_kernel(
    const float* __restrict__ t1, const float* __restrict__ W2,
    const float* __restrict__ b2, float* __restrict__ out)
{
    int gw = (blockIdx.x * blockDim.x + threadIdx.x) >> 5;
    int lane = threadIdx.x & 31;
    if (gw >= NN) return;
    const float* row = t1 + (size_t)gw * 128;
    float acc = 0.f;
#pragma unroll
    for (int k = lane; k < 128; k += 32) acc += row[k] * W2[k];
#pragma unroll
    for (int off = 16; off; off >>= 1) acc += __shfl_xor_sync(0xffffffffu, acc, off);
    if (lane == 0) out[gw] = acc + b2[0];
}

// ---------------- launch ----------------
extern "C" void kernel_launch(void* const* d_in, const int* in_sizes, int n_in,
                              void* d_out, int out_size)
{
    const float* x         = (const float*)d_in[0];
    const int*   ei        = (const int*)  d_in[1];
    const float* edge_attr = (const float*)d_in[2];
    const float* node_W    = (const float*)d_in[3];
    const float* node_b    = (const float*)d_in[4];
    const float* edge_W    = (const float*)d_in[5];
    const float* edge_b    = (const float*)d_in[6];
    const float* Wl        = (const float*)d_in[7];
    const float* bl        = (const float*)d_in[8];
    const float* Wr        = (const float*)d_in[9];
    const float* br        = (const float*)d_in[10];
    const float* We        = (const float*)d_in[11];
    const float* att       = (const float*)d_in[12];
    const float* conv_b    = (const float*)d_in[13];
    const float* Weu       = (const float*)d_in[14];
    const float* beu       = (const float*)d_in[15];
    const float* bn_g      = (const float*)d_in[16];
    const float* bn_b      = (const float*)d_in[17];
    const float* bn_rm     = (const float*)d_in[18];
    const float* bn_rv     = (const float*)d_in[19];
    const float* out_W1    = (const float*)d_in[20];
    const float* out_b1    = (const float*)d_in[21];
    const float* out_W2    = (const float*)d_in[22];
    const float* out_b2    = (const float*)d_in[23];

    const int* src = ei;
    const int* dst = ei + EE;

    float *h, *xl, *xr, *agg, *t1, *logits, *exv, *den, *R, *r, *A0, *A1, *b0, *b1;
    int *mx;
    cudaGetSymbolAddress((void**)&h,      g_h);
    cudaGetSymbolAddress((void**)&xl,     g_xl);
    cudaGetSymbolAddress((void**)&xr,     g_xr);
    cudaGetSymbolAddress((void**)&agg,    g_agg);
    cudaGetSymbolAddress((void**)&t1,     g_t1);
    cudaGetSymbolAddress((void**)&logits, g_logits);
    cudaGetSymbolAddress((void**)&exv,    g_exv);
    cudaGetSymbolAddress((void**)&mx,     g_mx);
    cudaGetSymbolAddress((void**)&den,    g_den);
    cudaGetSymbolAddress((void**)&R,      g_R);
    cudaGetSymbolAddress((void**)&r,      g_r);
    cudaGetSymbolAddress((void**)&A0,     g_A0);
    cudaGetSymbolAddress((void**)&A1,     g_A1);
    cudaGetSymbolAddress((void**)&b0,     g_b0);
    cudaGetSymbolAddress((void**)&b1,     g_b1);

    dim3 blk(256);
    dim3 gN((HID + 127) / 128, (NN + 127) / 128);
    dim3 gO((128 + 127) / 128, (NN + 127) / 128);

    // ---- edge-chain precompute: R_i = A_i @ We_i, r_i = b_i @ We_i ----
    {
        const float* Acur = edge_W;
        const float* bcur = edge_b;
        float* Abuf[2] = {A0, A1};
        float* bbuf[2] = {b0, b1};
        for (int i = 0; i < LAYERS; i++) {
            const float* Wei  = We  + (size_t)i * HID * HID;
            const float* Weui = Weu + (size_t)i * HID * HID;
            gemm10<<<10, 256>>>(Acur, Wei, R + (size_t)i * 10 * HID);
            vecmat<<<1, 256>>>(bcur, Wei, nullptr, r + (size_t)i * HID);
            if (i < LAYERS - 1) {
                gemm10<<<10, 256>>>(Acur, Weui, Abuf[i & 1]);
                vecmat<<<1, 256>>>(bcur, Weui, beu + (size_t)i * HID, bbuf[i & 1]);
                Acur = Abuf[i & 1];
                bcur = bbuf[i & 1];
            }
        }
    }

    // node encoder
    sgemm<<<gN, blk>>>(x, node_W, node_b, h, NN, HID, 13, 1.f);

    dim3 eblk(64, 4);
    int egrid = EE / 4;

    for (int i = 0; i < LAYERS; i++) {
        const float* Wli = Wl + (size_t)i * HID * HID;
        const float* Wri = Wr + (size_t)i * HID * HID;

        sgemm<<<gN, blk>>>(h, Wli, bl + i * HID, xl, NN, HID, HID, 1.f);
        sgemm<<<gN, blk>>>(h, Wri, br + i * HID, xr, NN, HID, HID, 1.f);

        init_softmax<<<(NN * HEADS + 255) / 256, 256>>>(mx, den, NN * HEADS);
        cudaMemsetAsync(agg, 0, (size_t)NN * HID * sizeof(float), 0);

        edge_logits_fused<<<egrid, eblk>>>(
            (const float4*)xl, (const float4*)xr, edge_attr,
            (const float4*)(R + (size_t)i * 10 * HID),
            (const float4*)(r + (size_t)i * HID),
            src, dst, (const float4*)(att + (size_t)i * HID), logits, mx);
        edge_exp_kernel<<<(EE * HEADS + 255) / 256, 256>>>(logits, dst, mx, exv, den);
        edge_agg_kernel<<<egrid, eblk>>>(
            (const float4*)xl, exv, den, src, dst, (float4*)agg);

        node_update_kernel<<<(NN * HID + 255) / 256, 256>>>(
            agg, conv_b + i * HID, bn_g + i * HID, bn_b + i * HID,
            bn_rm + i * HID, bn_rv + i * HID, h, i);
    }

    sgemm<<<gO, blk>>>(h, out_W1, out_b1, t1, NN, 128, HID, 0.01f);
    final_out_kernel<<<(NN * 32 + 255) / 256, 256>>>(t1, out_W2, out_b2, (float*)d_out);
}

// round 5
// speedup vs baseline: 11.0019x; 1.5642x over previous
#include <cuda_runtime.h>
#include <math.h>

#define NN 30000
#define EE 480000
#define HID 256
#define HEADS 8
#define LAYERS 6
#define BN_EPS 1e-5f

// ---------------- scratch ----------------
__device__ float g_h[NN * HID];
__device__ float g_xl[NN * HID];
__device__ float g_xr[NN * HID];
__device__ float g_agg[NN * HID];
__device__ float g_t1[NN * 128];
__device__ float g_exv[EE * HEADS];
__device__ float g_den[NN * HEADS];
// edge-chain precompute: ep_i = edge_attr @ R_i + r_i
__device__ float g_R[LAYERS * 10 * HID];
__device__ float g_r[LAYERS * HID];
__device__ float g_Ach[LAYERS * 10 * HID];
__device__ float g_bch[LAYERS * HID];

// ---------------- generic SGEMM (encoder K=13, final N=128) ----------------
__global__ __launch_bounds__(256) void sgemm(
    const float* __restrict__ A, const float* __restrict__ B,
    const float* __restrict__ bias, float* __restrict__ C,
    int M, int N, int K, float slope)
{
    const int BM = 128, BNt = 128, BK = 8;
    __shared__ float As[BK][BM];
    __shared__ float Bs[BK][BNt];
    int tid = threadIdx.x;
    int tx = tid & 15, ty = tid >> 4;
    int rowBase = blockIdx.y * BM, colBase = blockIdx.x * BNt;
    float acc[8][8];
#pragma unroll
    for (int i = 0; i < 8; i++)
#pragma unroll
        for (int j = 0; j < 8; j++) acc[i][j] = 0.f;
    for (int k0 = 0; k0 < K; k0 += BK) {
#pragma unroll
        for (int it = 0; it < 4; it++) {
            int idx = tid + it * 256;
            int m = idx >> 3, kk = idx & 7;
            int gr = rowBase + m, gc = k0 + kk;
            As[kk][m] = (gr < M && gc < K) ? A[(size_t)gr * K + gc] : 0.f;
        }
#pragma unroll
        for (int it = 0; it < 4; it++) {
            int idx = tid + it * 256;
            int kk = idx >> 7, n = idx & 127;
            int gr = k0 + kk, gc = colBase + n;
            Bs[kk][n] = (gr < K && gc < N) ? B[(size_t)gr * N + gc] : 0.f;
        }
        __syncthreads();
#pragma unroll
        for (int kk = 0; kk < BK; kk++) {
            float a[8], b[8];
#pragma unroll
            for (int i = 0; i < 8; i++) a[i] = As[kk][ty * 8 + i];
#pragma unroll
            for (int j = 0; j < 8; j++) b[j] = Bs[kk][tx * 8 + j];
#pragma unroll
            for (int i = 0; i < 8; i++)
#pragma unroll
                for (int j = 0; j < 8; j++) acc[i][j] += a[i] * b[j];
        }
        __syncthreads();
    }
#pragma unroll
    for (int i = 0; i < 8; i++) {
        int gr = rowBase + ty * 8 + i;
        if (gr >= M) continue;
#pragma unroll
        for (int j = 0; j < 8; j++) {
            int gc = colBase + tx * 8 + j;
            if (gc >= N) continue;
            float v = acc[i][j];
            if (bias) v += bias[gc];
            v = (v >= 0.f) ? v : slope * v;
            C[(size_t)gr * N + gc] = v;
        }
    }
}

// ---------------- TF32 tensor-core GEMM: C[M,256] = A[M,256] @ B[256,256] + bias ----------------
// NOTE: cvt.rna.tf32.f32 requires a .b32 destination register (=r), not =f.
__device__ __forceinline__ float to_tf32(float x) {
    unsigned int u;
    asm("cvt.rna.tf32.f32 %0, %1;" : "=r"(u) : "f"(x));
    return __uint_as_float(u);
}

__global__ __launch_bounds__(256, 2) void gemm_tf32_256(
    const float* __restrict__ A, const float* __restrict__ B,
    const float* __restrict__ bias, float* __restrict__ C, int M)
{
    __shared__ float As[128][20];   // [m][k] pad -> conflict-free frag reads
    __shared__ float Bs[16][136];   // [k][n] pad 8

    int tid = threadIdx.x;
    int warp = tid >> 5, lane = tid & 31;
    int wm = (warp & 1) * 64;
    int wn = (warp >> 1) * 32;
    int rowBase = blockIdx.y * 128;
    int colBase = blockIdx.x * 128;
    int lr = lane >> 2;   // 0..7
    int lc = lane & 3;    // 0..3

    float acc[4][4][4];
#pragma unroll
    for (int a = 0; a < 4; a++)
#pragma unroll
        for (int b = 0; b < 4; b++)
#pragma unroll
            for (int cc = 0; cc < 4; cc++) acc[a][b][cc] = 0.f;

    for (int k0 = 0; k0 < 256; k0 += 16) {
        // issue all global loads first (MLP), then convert+store to smem
        float4 va[2], vb[2];
#pragma unroll
        for (int it = 0; it < 2; it++) {
            int idx = tid + it * 256;          // 0..511
            int r = idx >> 2;
            int kq = (idx & 3) << 2;
            int gr = rowBase + r;
            va[it] = make_float4(0.f, 0.f, 0.f, 0.f);
            if (gr < M) va[it] = *(const float4*)(A + (size_t)gr * 256 + k0 + kq);
        }
#pragma unroll
        for (int it = 0; it < 2; it++) {
            int idx = tid + it * 256;
            int kk = idx >> 5;                 // 0..15
            int nq = (idx & 31) << 2;
            vb[it] = *(const float4*)(B + (size_t)(k0 + kk) * 256 + colBase + nq);
        }
#pragma unroll
        for (int it = 0; it < 2; it++) {
            int idx = tid + it * 256;
            int r = idx >> 2;
            int kq = (idx & 3) << 2;
            float4 v = va[it];
            v.x = to_tf32(v.x); v.y = to_tf32(v.y);
            v.z = to_tf32(v.z); v.w = to_tf32(v.w);
            *(float4*)&As[r][kq] = v;
        }
#pragma unroll
        for (int it = 0; it < 2; it++) {
            int idx = tid + it * 256;
            int kk = idx >> 5;
            int nq = (idx & 31) << 2;
            float4 v = vb[it];
            v.x = to_tf32(v.x); v.y = to_tf32(v.y);
            v.z = to_tf32(v.z); v.w = to_tf32(v.w);
            *(float4*)&Bs[kk][nq] = v;
        }
        __syncthreads();
#pragma unroll
        for (int kk = 0; kk < 16; kk += 8) {
            unsigned int af[4][4], bf[4][2];
#pragma unroll
            for (int mt = 0; mt < 4; mt++) {
                int m0 = wm + mt * 16;
                af[mt][0] = __float_as_uint(As[m0 + lr][kk + lc]);
                af[mt][1] = __float_as_uint(As[m0 + 8 + lr][kk + lc]);
                af[mt][2] = __float_as_uint(As[m0 + lr][kk + 4 + lc]);
                af[mt][3] = __float_as_uint(As[m0 + 8 + lr][kk + 4 + lc]);
            }
#pragma unroll
            for (int nt = 0; nt < 4; nt++) {
                int n0 = wn + nt * 8;
                bf[nt][0] = __float_as_uint(Bs[kk + lc][n0 + lr]);
                bf[nt][1] = __float_as_uint(Bs[kk + 4 + lc][n0 + lr]);
            }
#pragma unroll
            for (int mt = 0; mt < 4; mt++)
#pragma unroll
                for (int nt = 0; nt < 4; nt++) {
                    asm volatile(
                        "mma.sync.aligned.m16n8k8.row.col.f32.tf32.tf32.f32 "
                        "{%0,%1,%2,%3}, {%4,%5,%6,%7}, {%8,%9}, {%0,%1,%2,%3};"
                        : "+f"(acc[mt][nt][0]), "+f"(acc[mt][nt][1]),
                          "+f"(acc[mt][nt][2]), "+f"(acc[mt][nt][3])
                        : "r"(af[mt][0]), "r"(af[mt][1]), "r"(af[mt][2]), "r"(af[mt][3]),
                          "r"(bf[nt][0]), "r"(bf[nt][1]));
                }
        }
        __syncthreads();
    }

#pragma unroll
    for (int mt = 0; mt < 4; mt++)
#pragma unroll
        for (int nt = 0; nt < 4; nt++) {
            int r0 = rowBase + wm + mt * 16 + lr;
            int c0 = colBase + wn + nt * 8 + lc * 2;
            float b0 = bias[c0], b1 = bias[c0 + 1];
            if (r0 < M) {
                C[(size_t)r0 * 256 + c0]     = acc[mt][nt][0] + b0;
                C[(size_t)r0 * 256 + c0 + 1] = acc[mt][nt][1] + b1;
            }
            if (r0 + 8 < M) {
                C[(size_t)(r0 + 8) * 256 + c0]     = acc[mt][nt][2] + b0;
                C[(size_t)(r0 + 8) * 256 + c0 + 1] = acc[mt][nt][3] + b1;
            }
        }
}

// ---------------- precompute: sequential A/b chain (one block) ----------------
__global__ __launch_bounds__(256) void chain_kernel(
    const float* __restrict__ edge_W, const float* __restrict__ edge_b,
    const float* __restrict__ Weu, const float* __restrict__ beu,
    float* __restrict__ Ach, float* __restrict__ bch)
{
    __shared__ float Aw[10][HID];
    __shared__ float bw[HID];
    int c = threadIdx.x;
#pragma unroll
    for (int r = 0; r < 10; r++) Aw[r][c] = edge_W[r * HID + c];
    bw[c] = edge_b[c];
    __syncthreads();
#pragma unroll
    for (int r = 0; r < 10; r++) Ach[r * HID + c] = Aw[r][c];
    bch[c] = bw[c];
    for (int i = 0; i < LAYERS - 1; i++) {
        const float* W = Weu + (size_t)i * HID * HID;
        float acc[10];
#pragma unroll
        for (int r = 0; r < 10; r++) acc[r] = 0.f;
        float accB = beu[i * HID + c];
        for (int k = 0; k < HID; k++) {
            float w = W[(size_t)k * HID + c];
#pragma unroll
            for (int r = 0; r < 10; r++) acc[r] += Aw[r][k] * w;
            accB += bw[k] * w;
        }
        __syncthreads();
#pragma unroll
        for (int r = 0; r < 10; r++) Aw[r][c] = acc[r];
        bw[c] = accB;
        __syncthreads();
        float* Ao = Ach + (size_t)(i + 1) * 10 * HID;
#pragma unroll
        for (int r = 0; r < 10; r++) Ao[r * HID + c] = acc[r];
        bch[(i + 1) * HID + c] = accB;
    }
}

// ---------------- precompute: R_i = A_i @ We_i, r_i = b_i @ We_i ----------------
__global__ __launch_bounds__(256) void proj_kernel(
    const float* __restrict__ Ach, const float* __restrict__ bch,
    const float* __restrict__ We, float* __restrict__ R, float* __restrict__ rr)
{
    int i = blockIdx.x;
    int c = threadIdx.x;
    __shared__ float Aw[10][HID];
    __shared__ float bw[HID];
#pragma unroll
    for (int r = 0; r < 10; r++) Aw[r][c] = Ach[(size_t)i * 10 * HID + r * HID + c];
    bw[c] = bch[i * HID + c];
    __syncthreads();
    const float* W = We + (size_t)i * HID * HID;
    float acc[10];
#pragma unroll
    for (int r = 0; r < 10; r++) acc[r] = 0.f;
    float accB = 0.f;
    for (int k = 0; k < HID; k++) {
        float w = W[(size_t)k * HID + c];
#pragma unroll
        for (int r = 0; r < 10; r++) acc[r] += Aw[r][k] * w;
        accB += bw[k] * w;
    }
#pragma unroll
    for (int r = 0; r < 10; r++) R[(size_t)i * 10 * HID + r * HID + c] = acc[r];
    rr[i * HID + c] = accB;
}

__device__ __forceinline__ float leaky02(float v) { return v >= 0.f ? v : 0.2f * v; }

// ---------------- pass A: fused ep + logits + exp + den (no max; shift-invariant) ----------------
__global__ __launch_bounds__(256) void edge_logits_fused(
    const float4* __restrict__ xl4, const float4* __restrict__ xr4,
    const float* __restrict__ eattr, const float4* __restrict__ R4,
    const float4* __restrict__ rv4, const int* __restrict__ src,
    const int* __restrict__ dst, const float4* __restrict__ att4,
    float* __restrict__ exv, float* __restrict__ den)
{
    int e = blockIdx.x * 4 + threadIdx.y;
    int t = threadIdx.x;
    int s = src[e], d = dst[e];
    float4 acc = rv4[t];
    const float* ea = eattr + (size_t)e * 10;
#pragma unroll
    for (int k = 0; k < 10; k++) {
        float a = ea[k];
        float4 rr = R4[k * 64 + t];
        acc.x += a * rr.x; acc.y += a * rr.y; acc.z += a * rr.z; acc.w += a * rr.w;
    }
    float4 l = xl4[(size_t)s * 64 + t];
    float4 rr = xr4[(size_t)d * 64 + t];
    float4 m;
    m.x = leaky02(l.x + rr.x + acc.x);
    m.y = leaky02(l.y + rr.y + acc.y);
    m.z = leaky02(l.z + rr.z + acc.z);
    m.w = leaky02(l.w + rr.w + acc.w);
    float4 at = att4[t];
    float p = m.x * at.x + m.y * at.y + m.z * at.z + m.w * at.w;
#pragma unroll
    for (int off = 4; off; off >>= 1) p += __shfl_xor_sync(0xffffffffu, p, off);
    if ((t & 7) == 0) {
        int h = t >> 3;
        float v = expf(p);
        exv[(size_t)e * HEADS + h] = v;
        atomicAdd(&den[d * HEADS + h], v);
    }
}

// ---------------- pass C: weighted aggregation (vector atomics) ----------------
__global__ __launch_bounds__(256) void edge_agg_kernel(
    const float4* __restrict__ xl4, const float* __restrict__ exv,
    const float* __restrict__ den, const int* __restrict__ src,
    const int* __restrict__ dst, float4* __restrict__ agg4)
{
    int e = blockIdx.x * 4 + threadIdx.y;
    int t = threadIdx.x;
    int s = src[e], d = dst[e];
    int h = t >> 3;
    float alpha = exv[(size_t)e * HEADS + h] / (den[d * HEADS + h] + 1e-16f);
    float4 v = xl4[(size_t)s * 64 + t];
    v.x *= alpha; v.y *= alpha; v.z *= alpha; v.w *= alpha;
    float4* addr = agg4 + (size_t)d * 64 + t;
    asm volatile("red.global.add.v4.f32 [%0], {%1, %2, %3, %4};"
                 :: "l"(addr), "f"(v.x), "f"(v.y), "f"(v.z), "f"(v.w) : "memory");
}

// ---------------- node update ----------------
__global__ void node_update_kernel(
    const float* __restrict__ agg, const float* __restrict__ conv_b,
    const float* __restrict__ bn_g, const float* __restrict__ bn_b,
    const float* __restrict__ bn_rm, const float* __restrict__ bn_rv,
    float* __restrict__ h, int layer)
{
    int i = blockIdx.x * blockDim.x + threadIdx.x;
    if (i >= NN * HID) return;
    int c = i & (HID - 1);
    float v = agg[i] + conv_b[c];
    v = (v - bn_rm[c]) * rsqrtf(bn_rv[c] + BN_EPS) * bn_g[c] + bn_b[c];
    v = (v >= 0.f) ? v : 0.01f * v;
    if (layer >= 1) v += h[i];
    h[i] = v;
}

// ---------------- final projection ----------------
__global__ void final_out_kernel(
    const float* __restrict__ t1, const float* __restrict__ W2,
    const float* __restrict__ b2, float* __restrict__ out)
{
    int gw = (blockIdx.x * blockDim.x + threadIdx.x) >> 5;
    int lane = threadIdx.x & 31;
    if (gw >= NN) return;
    const float* row = t1 + (size_t)gw * 128;
    float acc = 0.f;
#pragma unroll
    for (int k = lane; k < 128; k += 32) acc += row[k] * W2[k];
#pragma unroll
    for (int off = 16; off; off >>= 1) acc += __shfl_xor_sync(0xffffffffu, acc, off);
    if (lane == 0) out[gw] = acc + b2[0];
}

// ---------------- launch ----------------
extern "C" void kernel_launch(void* const* d_in, const int* in_sizes, int n_in,
                              void* d_out, int out_size)
{
    const float* x         = (const float*)d_in[0];
    const int*   ei        = (const int*)  d_in[1];
    const float* edge_attr = (const float*)d_in[2];
    const float* node_W    = (const float*)d_in[3];
    const float* node_b    = (const float*)d_in[4];
    const float* edge_W    = (const float*)d_in[5];
    const float* edge_b    = (const float*)d_in[6];
    const float* Wl        = (const float*)d_in[7];
    const float* bl        = (const float*)d_in[8];
    const float* Wr        = (const float*)d_in[9];
    const float* br        = (const float*)d_in[10];
    const float* We        = (const float*)d_in[11];
    const float* att       = (const float*)d_in[12];
    const float* conv_b    = (const float*)d_in[13];
    const float* Weu       = (const float*)d_in[14];
    const float* beu       = (const float*)d_in[15];
    const float* bn_g      = (const float*)d_in[16];
    const float* bn_b      = (const float*)d_in[17];
    const float* bn_rm     = (const float*)d_in[18];
    const float* bn_rv     = (const float*)d_in[19];
    const float* out_W1    = (const float*)d_in[20];
    const float* out_b1    = (const float*)d_in[21];
    const float* out_W2    = (const float*)d_in[22];
    const float* out_b2    = (const float*)d_in[23];

    const int* src = ei;
    const int* dst = ei + EE;

    float *h, *xl, *xr, *agg, *t1, *exv, *den, *R, *r, *Ach, *bch;
    cudaGetSymbolAddress((void**)&h,   g_h);
    cudaGetSymbolAddress((void**)&xl,  g_xl);
    cudaGetSymbolAddress((void**)&xr,  g_xr);
    cudaGetSymbolAddress((void**)&agg, g_agg);
    cudaGetSymbolAddress((void**)&t1,  g_t1);
    cudaGetSymbolAddress((void**)&exv, g_exv);
    cudaGetSymbolAddress((void**)&den, g_den);
    cudaGetSymbolAddress((void**)&R,   g_R);
    cudaGetSymbolAddress((void**)&r,   g_r);
    cudaGetSymbolAddress((void**)&Ach, g_Ach);
    cudaGetSymbolAddress((void**)&bch, g_bch);

    dim3 blk(256);
    dim3 gN((HID + 127) / 128, (NN + 127) / 128);
    dim3 gT(2, (NN + 127) / 128);
    dim3 gO(1, (NN + 127) / 128);

    // edge-chain precompute (2 launches total)
    chain_kernel<<<1, 256>>>(edge_W, edge_b, Weu, beu, Ach, bch);
    proj_kernel<<<LAYERS, 256>>>(Ach, bch, We, R, r);

    // node encoder (K=13, generic path)
    sgemm<<<gN, blk>>>(x, node_W, node_b, h, NN, HID, 13, 1.f);

    dim3 eblk(64, 4);
    int egrid = EE / 4;

    for (int i = 0; i < LAYERS; i++) {
        const float* Wli = Wl + (size_t)i * HID * HID;
        const float* Wri = Wr + (size_t)i * HID * HID;

        gemm_tf32_256<<<gT, blk>>>(h, Wli, bl + i * HID, xl, NN);
        gemm_tf32_256<<<gT, blk>>>(h, Wri, br + i * HID, xr, NN);

        cudaMemsetAsync(den, 0, (size_t)NN * HEADS * sizeof(float), 0);
        cudaMemsetAsync(agg, 0, (size_t)NN * HID * sizeof(float), 0);

        edge_logits_fused<<<egrid, eblk>>>(
            (const float4*)xl, (const float4*)xr, edge_attr,
            (const float4*)(R + (size_t)i * 10 * HID),
            (const float4*)(r + (size_t)i * HID),
            src, dst, (const float4*)(att + (size_t)i * HID), exv, den);
        edge_agg_kernel<<<egrid, eblk>>>(
            (const float4*)xl, exv, den, src, dst, (float4*)agg);

        node_update_kernel<<<(NN * HID + 255) / 256, 256>>>(
            agg, conv_b + i * HID, bn_g + i * HID, bn_b + i * HID,
            bn_rm + i * HID, bn_rv + i * HID, h, i);
    }

    sgemm<<<gO, blk>>>(h, out_W1, out_b1, t1, NN, 128, HID, 0.01f);
    final_out_kernel<<<(NN * 32 + 255) / 256, 256>>>(t1, out_W2, out_b2, (float*)d_out);
}

// round 6
// speedup vs baseline: 14.0986x; 1.2815x over previous
#include <cuda_runtime.h>
#include <math.h>

#define NN 30000
#define EE 480000
#define HID 256
#define HEADS 8
#define LAYERS 6
#define BN_EPS 1e-5f

// ---------------- scratch ----------------
__device__ float g_h[NN * HID];
__device__ float g_xl[NN * HID];
__device__ float g_xr[NN * HID];
__device__ float g_agg[NN * HID];
__device__ float g_t1[NN * 128];
__device__ float g_den[NN * HEADS];
// edge-chain precompute: ep_i = edge_attr @ R_i + r_i
__device__ float g_R[LAYERS * 10 * HID];
__device__ float g_r[LAYERS * HID];
__device__ float g_Ach[LAYERS * 10 * HID];
__device__ float g_bch[LAYERS * HID];

// ---------------- generic SGEMM (encoder K=13, final N=128) ----------------
__global__ __launch_bounds__(256) void sgemm(
    const float* __restrict__ A, const float* __restrict__ B,
    const float* __restrict__ bias, float* __restrict__ C,
    int M, int N, int K, float slope)
{
    const int BM = 128, BNt = 128, BK = 8;
    __shared__ float As[BK][BM];
    __shared__ float Bs[BK][BNt];
    int tid = threadIdx.x;
    int tx = tid & 15, ty = tid >> 4;
    int rowBase = blockIdx.y * BM, colBase = blockIdx.x * BNt;
    float acc[8][8];
#pragma unroll
    for (int i = 0; i < 8; i++)
#pragma unroll
        for (int j = 0; j < 8; j++) acc[i][j] = 0.f;
    for (int k0 = 0; k0 < K; k0 += BK) {
#pragma unroll
        for (int it = 0; it < 4; it++) {
            int idx = tid + it * 256;
            int m = idx >> 3, kk = idx & 7;
            int gr = rowBase + m, gc = k0 + kk;
            As[kk][m] = (gr < M && gc < K) ? A[(size_t)gr * K + gc] : 0.f;
        }
#pragma unroll
        for (int it = 0; it < 4; it++) {
            int idx = tid + it * 256;
            int kk = idx >> 7, n = idx & 127;
            int gr = k0 + kk, gc = colBase + n;
            Bs[kk][n] = (gr < K && gc < N) ? B[(size_t)gr * N + gc] : 0.f;
        }
        __syncthreads();
#pragma unroll
        for (int kk = 0; kk < BK; kk++) {
            float a[8], b[8];
#pragma unroll
            for (int i = 0; i < 8; i++) a[i] = As[kk][ty * 8 + i];
#pragma unroll
            for (int j = 0; j < 8; j++) b[j] = Bs[kk][tx * 8 + j];
#pragma unroll
            for (int i = 0; i < 8; i++)
#pragma unroll
                for (int j = 0; j < 8; j++) acc[i][j] += a[i] * b[j];
        }
        __syncthreads();
    }
#pragma unroll
    for (int i = 0; i < 8; i++) {
        int gr = rowBase + ty * 8 + i;
        if (gr >= M) continue;
#pragma unroll
        for (int j = 0; j < 8; j++) {
            int gc = colBase + tx * 8 + j;
            if (gc >= N) continue;
            float v = acc[i][j];
            if (bias) v += bias[gc];
            v = (v >= 0.f) ? v : slope * v;
            C[(size_t)gr * N + gc] = v;
        }
    }
}

// ---------------- TF32 tensor-core GEMM (dual output: Wl->xl, Wr->xr) ----------------
__device__ __forceinline__ float to_tf32(float x) {
    unsigned int u;
    asm("cvt.rna.tf32.f32 %0, %1;" : "=r"(u) : "f"(x));
    return __uint_as_float(u);
}

__global__ __launch_bounds__(256, 2) void gemm_tf32_dual(
    const float* __restrict__ A,
    const float* __restrict__ B0, const float* __restrict__ bias0, float* __restrict__ C0,
    const float* __restrict__ B1, const float* __restrict__ bias1, float* __restrict__ C1,
    int M)
{
    __shared__ float As[128][20];
    __shared__ float Bs[16][136];

    int which = blockIdx.x >> 1;               // 0: (B0,C0)  1: (B1,C1)
    const float* B    = which ? B1 : B0;
    const float* bias = which ? bias1 : bias0;
    float*       C    = which ? C1 : C0;

    int tid = threadIdx.x;
    int warp = tid >> 5, lane = tid & 31;
    int wm = (warp & 1) * 64;
    int wn = (warp >> 1) * 32;
    int rowBase = blockIdx.y * 128;
    int colBase = (blockIdx.x & 1) * 128;
    int lr = lane >> 2;
    int lc = lane & 3;

    float acc[4][4][4];
#pragma unroll
    for (int a = 0; a < 4; a++)
#pragma unroll
        for (int b = 0; b < 4; b++)
#pragma unroll
            for (int cc = 0; cc < 4; cc++) acc[a][b][cc] = 0.f;

    for (int k0 = 0; k0 < 256; k0 += 16) {
        float4 va[2], vb[2];
#pragma unroll
        for (int it = 0; it < 2; it++) {
            int idx = tid + it * 256;
            int r = idx >> 2;
            int kq = (idx & 3) << 2;
            int gr = rowBase + r;
            va[it] = make_float4(0.f, 0.f, 0.f, 0.f);
            if (gr < M) va[it] = *(const float4*)(A + (size_t)gr * 256 + k0 + kq);
        }
#pragma unroll
        for (int it = 0; it < 2; it++) {
            int idx = tid + it * 256;
            int kk = idx >> 5;
            int nq = (idx & 31) << 2;
            vb[it] = *(const float4*)(B + (size_t)(k0 + kk) * 256 + colBase + nq);
        }
#pragma unroll
        for (int it = 0; it < 2; it++) {
            int idx = tid + it * 256;
            int r = idx >> 2;
            int kq = (idx & 3) << 2;
            float4 v = va[it];
            v.x = to_tf32(v.x); v.y = to_tf32(v.y);
            v.z = to_tf32(v.z); v.w = to_tf32(v.w);
            *(float4*)&As[r][kq] = v;
        }
#pragma unroll
        for (int it = 0; it < 2; it++) {
            int idx = tid + it * 256;
            int kk = idx >> 5;
            int nq = (idx & 31) << 2;
            float4 v = vb[it];
            v.x = to_tf32(v.x); v.y = to_tf32(v.y);
            v.z = to_tf32(v.z); v.w = to_tf32(v.w);
            *(float4*)&Bs[kk][nq] = v;
        }
        __syncthreads();
#pragma unroll
        for (int kk = 0; kk < 16; kk += 8) {
            unsigned int af[4][4], bf[4][2];
#pragma unroll
            for (int mt = 0; mt < 4; mt++) {
                int m0 = wm + mt * 16;
                af[mt][0] = __float_as_uint(As[m0 + lr][kk + lc]);
                af[mt][1] = __float_as_uint(As[m0 + 8 + lr][kk + lc]);
                af[mt][2] = __float_as_uint(As[m0 + lr][kk + 4 + lc]);
                af[mt][3] = __float_as_uint(As[m0 + 8 + lr][kk + 4 + lc]);
            }
#pragma unroll
            for (int nt = 0; nt < 4; nt++) {
                int n0 = wn + nt * 8;
                bf[nt][0] = __float_as_uint(Bs[kk + lc][n0 + lr]);
                bf[nt][1] = __float_as_uint(Bs[kk + 4 + lc][n0 + lr]);
            }
#pragma unroll
            for (int mt = 0; mt < 4; mt++)
#pragma unroll
                for (int nt = 0; nt < 4; nt++) {
                    asm volatile(
                        "mma.sync.aligned.m16n8k8.row.col.f32.tf32.tf32.f32 "
                        "{%0,%1,%2,%3}, {%4,%5,%6,%7}, {%8,%9}, {%0,%1,%2,%3};"
                        : "+f"(acc[mt][nt][0]), "+f"(acc[mt][nt][1]),
                          "+f"(acc[mt][nt][2]), "+f"(acc[mt][nt][3])
                        : "r"(af[mt][0]), "r"(af[mt][1]), "r"(af[mt][2]), "r"(af[mt][3]),
                          "r"(bf[nt][0]), "r"(bf[nt][1]));
                }
        }
        __syncthreads();
    }

#pragma unroll
    for (int mt = 0; mt < 4; mt++)
#pragma unroll
        for (int nt = 0; nt < 4; nt++) {
            int r0 = rowBase + wm + mt * 16 + lr;
            int c0 = colBase + wn + nt * 8 + lc * 2;
            float b0 = bias[c0], b1 = bias[c0 + 1];
            if (r0 < M) {
                C[(size_t)r0 * 256 + c0]     = acc[mt][nt][0] + b0;
                C[(size_t)r0 * 256 + c0 + 1] = acc[mt][nt][1] + b1;
            }
            if (r0 + 8 < M) {
                C[(size_t)(r0 + 8) * 256 + c0]     = acc[mt][nt][2] + b0;
                C[(size_t)(r0 + 8) * 256 + c0 + 1] = acc[mt][nt][3] + b1;
            }
        }
}

// ---------------- precompute: sequential A/b chain (one block) ----------------
__global__ __launch_bounds__(256) void chain_kernel(
    const float* __restrict__ edge_W, const float* __restrict__ edge_b,
    const float* __restrict__ Weu, const float* __restrict__ beu,
    float* __restrict__ Ach, float* __restrict__ bch)
{
    __shared__ float Aw[10][HID];
    __shared__ float bw[HID];
    int c = threadIdx.x;
#pragma unroll
    for (int r = 0; r < 10; r++) Aw[r][c] = edge_W[r * HID + c];
    bw[c] = edge_b[c];
    __syncthreads();
#pragma unroll
    for (int r = 0; r < 10; r++) Ach[r * HID + c] = Aw[r][c];
    bch[c] = bw[c];
    for (int i = 0; i < LAYERS - 1; i++) {
        const float* W = Weu + (size_t)i * HID * HID;
        float acc[10];
#pragma unroll
        for (int r = 0; r < 10; r++) acc[r] = 0.f;
        float accB = beu[i * HID + c];
        for (int k = 0; k < HID; k++) {
            float w = W[(size_t)k * HID + c];
#pragma unroll
            for (int r = 0; r < 10; r++) acc[r] += Aw[r][k] * w;
            accB += bw[k] * w;
        }
        __syncthreads();
#pragma unroll
        for (int r = 0; r < 10; r++) Aw[r][c] = acc[r];
        bw[c] = accB;
        __syncthreads();
        float* Ao = Ach + (size_t)(i + 1) * 10 * HID;
#pragma unroll
        for (int r = 0; r < 10; r++) Ao[r * HID + c] = acc[r];
        bch[(i + 1) * HID + c] = accB;
    }
}

// ---------------- precompute: R_i = A_i @ We_i, r_i = b_i @ We_i ----------------
__global__ __launch_bounds__(256) void proj_kernel(
    const float* __restrict__ Ach, const float* __restrict__ bch,
    const float* __restrict__ We, float* __restrict__ R, float* __restrict__ rr)
{
    int i = blockIdx.x;
    int c = threadIdx.x;
    __shared__ float Aw[10][HID];
    __shared__ float bw[HID];
#pragma unroll
    for (int r = 0; r < 10; r++) Aw[r][c] = Ach[(size_t)i * 10 * HID + r * HID + c];
    bw[c] = bch[i * HID + c];
    __syncthreads();
    const float* W = We + (size_t)i * HID * HID;
    float acc[10];
#pragma unroll
    for (int r = 0; r < 10; r++) acc[r] = 0.f;
    float accB = 0.f;
    for (int k = 0; k < HID; k++) {
        float w = W[(size_t)k * HID + c];
#pragma unroll
        for (int r = 0; r < 10; r++) acc[r] += Aw[r][k] * w;
        accB += bw[k] * w;
    }
#pragma unroll
    for (int r = 0; r < 10; r++) R[(size_t)i * 10 * HID + r * HID + c] = acc[r];
    rr[i * HID + c] = accB;
}

__device__ __forceinline__ float leaky02(float v) { return v >= 0.f ? v : 0.2f * v; }

// ---------------- SINGLE fused edge pass: ep + logits + exp + den + unnormalized agg ----------------
// agg_un[d] += xl[s] * exv_e ; den[d,h] += exv_e ; normalization deferred to node_update.
__global__ __launch_bounds__(256) void edge_fused_kernel(
    const float4* __restrict__ xl4, const float4* __restrict__ xr4,
    const float* __restrict__ eattr, const float4* __restrict__ R4,
    const float4* __restrict__ rv4, const int* __restrict__ src,
    const int* __restrict__ dst, const float4* __restrict__ att4,
    float* __restrict__ den, float4* __restrict__ agg4)
{
    int e = blockIdx.x * 4 + threadIdx.y;
    int t = threadIdx.x;                       // 0..63 -> channels 4t..4t+3
    int s = src[e], d = dst[e];

    // ep = edge_attr[e] (10) @ R + r
    float4 acc = rv4[t];
    const float* ea = eattr + (size_t)e * 10;
#pragma unroll
    for (int k = 0; k < 10; k++) {
        float a = ea[k];
        float4 rr = R4[k * 64 + t];
        acc.x += a * rr.x; acc.y += a * rr.y; acc.z += a * rr.z; acc.w += a * rr.w;
    }
    float4 l = xl4[(size_t)s * 64 + t];
    float4 rr = xr4[(size_t)d * 64 + t];
    float4 m;
    m.x = leaky02(l.x + rr.x + acc.x);
    m.y = leaky02(l.y + rr.y + acc.y);
    m.z = leaky02(l.z + rr.z + acc.z);
    m.w = leaky02(l.w + rr.w + acc.w);
    float4 at = att4[t];
    float p = m.x * at.x + m.y * at.y + m.z * at.z + m.w * at.w;
    // butterfly over the 8-lane head group: every lane ends with the head logit
#pragma unroll
    for (int off = 4; off; off >>= 1) p += __shfl_xor_sync(0xffffffffu, p, off);
    float v = expf(p);
    if ((t & 7) == 0) {
        int h = t >> 3;
        atomicAdd(&den[d * HEADS + h], v);
    }
    float4 w;
    w.x = l.x * v; w.y = l.y * v; w.z = l.z * v; w.w = l.w * v;
    float4* addr = agg4 + (size_t)d * 64 + t;
    asm volatile("red.global.add.v4.f32 [%0], {%1, %2, %3, %4};"
                 :: "l"(addr), "f"(w.x), "f"(w.y), "f"(w.z), "f"(w.w) : "memory");
}

// ---------------- node update: normalize, conv bias, BN(eval), leaky, residual ----------------
__global__ void node_update_kernel(
    const float* __restrict__ agg, const float* __restrict__ den,
    const float* __restrict__ conv_b,
    const float* __restrict__ bn_g, const float* __restrict__ bn_b,
    const float* __restrict__ bn_rm, const float* __restrict__ bn_rv,
    float* __restrict__ h, int layer)
{
    int i = blockIdx.x * blockDim.x + threadIdx.x;
    if (i >= NN * HID) return;
    int c = i & (HID - 1);
    int node = i >> 8;
    int hd = c >> 5;
    float v = agg[i] / (den[node * HEADS + hd] + 1e-16f) + conv_b[c];
    v = (v - bn_rm[c]) * rsqrtf(bn_rv[c] + BN_EPS) * bn_g[c] + bn_b[c];
    v = (v >= 0.f) ? v : 0.01f * v;
    if (layer >= 1) v += h[i];
    h[i] = v;
}

// ---------------- final projection ----------------
__global__ void final_out_kernel(
    const float* __restrict__ t1, const float* __restrict__ W2,
    const float* __restrict__ b2, float* __restrict__ out)
{
    int gw = (blockIdx.x * blockDim.x + threadIdx.x) >> 5;
    int lane = threadIdx.x & 31;
    if (gw >= NN) return;
    const float* row = t1 + (size_t)gw * 128;
    float acc = 0.f;
#pragma unroll
    for (int k = lane; k < 128; k += 32) acc += row[k] * W2[k];
#pragma unroll
    for (int off = 16; off; off >>= 1) acc += __shfl_xor_sync(0xffffffffu, acc, off);
    if (lane == 0) out[gw] = acc + b2[0];
}

// ---------------- launch ----------------
extern "C" void kernel_launch(void* const* d_in, const int* in_sizes, int n_in,
                              void* d_out, int out_size)
{
    const float* x         = (const float*)d_in[0];
    const int*   ei        = (const int*)  d_in[1];
    const float* edge_attr = (const float*)d_in[2];
    const float* node_W    = (const float*)d_in[3];
    const float* node_b    = (const float*)d_in[4];
    const float* edge_W    = (const float*)d_in[5];
    const float* edge_b    = (const float*)d_in[6];
    const float* Wl        = (const float*)d_in[7];
    const float* bl        = (const float*)d_in[8];
    const float* Wr        = (const float*)d_in[9];
    const float* br        = (const float*)d_in[10];
    const float* We        = (const float*)d_in[11];
    const float* att       = (const float*)d_in[12];
    const float* conv_b    = (const float*)d_in[13];
    const float* Weu       = (const float*)d_in[14];
    const float* beu       = (const float*)d_in[15];
    const float* bn_g      = (const float*)d_in[16];
    const float* bn_b      = (const float*)d_in[17];
    const float* bn_rm     = (const float*)d_in[18];
    const float* bn_rv     = (const float*)d_in[19];
    const float* out_W1    = (const float*)d_in[20];
    const float* out_b1    = (const float*)d_in[21];
    const float* out_W2    = (const float*)d_in[22];
    const float* out_b2    = (const float*)d_in[23];

    const int* src = ei;
    const int* dst = ei + EE;

    float *h, *xl, *xr, *agg, *t1, *den, *R, *r, *Ach, *bch;
    cudaGetSymbolAddress((void**)&h,   g_h);
    cudaGetSymbolAddress((void**)&xl,  g_xl);
    cudaGetSymbolAddress((void**)&xr,  g_xr);
    cudaGetSymbolAddress((void**)&agg, g_agg);
    cudaGetSymbolAddress((void**)&t1,  g_t1);
    cudaGetSymbolAddress((void**)&den, g_den);
    cudaGetSymbolAddress((void**)&R,   g_R);
    cudaGetSymbolAddress((void**)&r,   g_r);
    cudaGetSymbolAddress((void**)&Ach, g_Ach);
    cudaGetSymbolAddress((void**)&bch, g_bch);

    dim3 blk(256);
    dim3 gN((HID + 127) / 128, (NN + 127) / 128);
    dim3 gD(4, (NN + 127) / 128);   // dual-output tf32 grid
    dim3 gO(1, (NN + 127) / 128);

    // edge-chain precompute (2 launches total)
    chain_kernel<<<1, 256>>>(edge_W, edge_b, Weu, beu, Ach, bch);
    proj_kernel<<<LAYERS, 256>>>(Ach, bch, We, R, r);

    // node encoder (K=13, generic path)
    sgemm<<<gN, blk>>>(x, node_W, node_b, h, NN, HID, 13, 1.f);

    dim3 eblk(64, 4);
    int egrid = EE / 4;

    for (int i = 0; i < LAYERS; i++) {
        const float* Wli = Wl + (size_t)i * HID * HID;
        const float* Wri = Wr + (size_t)i * HID * HID;

        gemm_tf32_dual<<<gD, blk>>>(h, Wli, bl + i * HID, xl,
                                       Wri, br + i * HID, xr, NN);

        cudaMemsetAsync(den, 0, (size_t)NN * HEADS * sizeof(float), 0);
        cudaMemsetAsync(agg, 0, (size_t)NN * HID * sizeof(float), 0);

        edge_fused_kernel<<<egrid, eblk>>>(
            (const float4*)xl, (const float4*)xr, edge_attr,
            (const float4*)(R + (size_t)i * 10 * HID),
            (const float4*)(r + (size_t)i * HID),
            src, dst, (const float4*)(att + (size_t)i * HID), den, (float4*)agg);

        node_update_kernel<<<(NN * HID + 255) / 256, 256>>>(
            agg, den, conv_b + i * HID, bn_g + i * HID, bn_b + i * HID,
            bn_rm + i * HID, bn_rv + i * HID, h, i);
    }

    sgemm<<<gO, blk>>>(h, out_W1, out_b1, t1, NN, 128, HID, 0.01f);
    final_out_kernel<<<(NN * 32 + 255) / 256, 256>>>(t1, out_W2, out_b2, (float*)d_out);
}